// round 17
// baseline (speedup 1.0000x reference)
#include <cuda_runtime.h>

// Problem constants (fixed shapes per reference setup_inputs)
#define N_IN   65536
#define BATCH  128
#define HALF_B 64
#define N_OUTP 65536
#define M_SAMP 131072   // N_OUT * degree, degree = 2
#define TN     32       // outputs per block in main-half kernel

// Scratch (device globals: allocation inside kernel_launch is forbidden)
__device__ __align__(16) float g_lo[(size_t)N_IN * HALF_B];  // batches 0..63, [n][b]
__device__ __align__(16) float g_hi[(size_t)N_IN * HALF_B];  // batches 64..127
__device__ __align__(16) int2  g_pairs[M_SAMP];              // {idx, bitcast(w)}

// smem layout for main-half role (and combo kernel size)
#define SM_STAGE 0            // TN x 1KB = 32768
#define SM_TILE  32768        // TN x 66 floats = 8448
#define SM_SP4   41216        // TN x 16 = 512
#define SM_MAIN  41728

// Replicate jnp.linspace(0,1,65536, float32): x[i] = fl(i * fl(1/65535)), x[last]=1.0
__device__ __forceinline__ float gridx(int i) {
    return (i == N_IN - 1) ? 1.0f : (float)i * (1.0f / 65535.0f);
}

// ---------------------------------------------------------------------------
// prep-half: clip + transpose a 128n x 32b tile of one batch-half into dst
// ([n][64] layout, rows 256B). XOR-swizzled float4 tile, conflict-free.
// ---------------------------------------------------------------------------
__device__ __forceinline__ void prep_half(const float* __restrict__ act,
                                          float* __restrict__ dst,
                                          int halfBase, int px, int py,
                                          int tid, char* raw) {
    float4 (*tile4)[32] = (float4(*)[32])raw;    // logical (b,c4) at [b][c4^((b>>2)&7)]
    const int n0 = px * 128;
    const int b0 = py * 32;                      // local b within half
    const int tx = tid & 31;
    const int ty = tid >> 5;
    const float4* a4 = (const float4*)act;       // row stride N_IN/4 = 16384
#pragma unroll
    for (int j = 0; j < 4; ++j) {
        int brow = ty + 8 * j;                   // local b: 0..31
        float4 v = __ldcs(&a4[(size_t)(halfBase + b0 + brow) * 16384 + (n0 >> 2) + tx]);
        v.x = __saturatef(v.x);
        v.y = __saturatef(v.y);
        v.z = __saturatef(v.z);
        v.w = __saturatef(v.w);
        tile4[brow][tx ^ ((brow >> 2) & 7)] = v;  // STS.128, conflict-free
    }
    __syncthreads();

    const int cx = tid & 7;                      // b-quad within 32-b tile
    const int n4 = tid >> 3;                     // n-quad 0..31
    float4 m0 = tile4[4 * cx + 0][n4 ^ cx];      // LDS.128, conflict-free
    float4 m1 = tile4[4 * cx + 1][n4 ^ cx];
    float4 m2 = tile4[4 * cx + 2][n4 ^ cx];
    float4 m3 = tile4[4 * cx + 3][n4 ^ cx];

    float4* t4 = (float4*)dst;                   // row stride HALF_B/4 = 16
    size_t base = (size_t)(n0 + 4 * n4) * 16 + (b0 >> 2) + cx;
    t4[base + 0 * 16] = make_float4(m0.x, m1.x, m2.x, m3.x);
    t4[base + 1 * 16] = make_float4(m0.y, m1.y, m2.y, m3.y);
    t4[base + 2 * 16] = make_float4(m0.z, m1.z, m2.z, m3.z);
    t4[base + 3 * 16] = make_float4(m0.w, m1.w, m2.w, m3.w);
}

// ---------------------------------------------------------------------------
// main-half: round-9 structure on a 64-batch half. 256 threads, TN=32 n/block.
// Per n: rows (i0,i0+1) = 512B contiguous + (i1,i1+1) = 512B contiguous.
// Lane l cp.asyncs bytes [16l,16l+16) of each 512B chunk; wait_group +
// __syncwarp orders cross-lane (within-warp) smem reads. float2 compute;
// coalesced epilogue.
// ---------------------------------------------------------------------------
__device__ __forceinline__ void main_half(float* __restrict__ out,
                                          const char* __restrict__ srcB,
                                          int rowBase, int mbx,
                                          int tid, char* raw) {
    float (*stage)[256] = (float(*)[256])(raw + SM_STAGE);   // [k][4 rows x 64 f]
    float (*tile)[66]   = (float(*)[66])(raw + SM_TILE);     // results [n][b]
    int4* sp4           = (int4*)(raw + SM_SP4);             // {i0,w0,i1,w1}
    const int w  = tid >> 5;             // warp 0..7, owns k = 4w..4w+3
    const int l  = tid & 31;
    const int n0 = mbx * TN;

    if (tid < TN) sp4[tid] = ((const int4*)g_pairs)[n0 + tid];
    __syncthreads();

    // --- issue: 2 commit-groups of 2 k each ---
#pragma unroll
    for (int g = 0; g < 2; ++g) {
#pragma unroll
        for (int j = 0; j < 2; ++j) {
            const int k = w * 4 + g * 2 + j;
            const int4 s = sp4[k];
            const char* p0 = srcB + (size_t)s.x * 256 + l * 16;  // rows i0,i0+1
            const char* p1 = srcB + (size_t)s.z * 256 + l * 16;  // rows i1,i1+1
            unsigned d = (unsigned)__cvta_generic_to_shared(&stage[k][0]) + l * 16;
            asm volatile("cp.async.cg.shared.global [%0], [%1], 16;\n" :: "r"(d),       "l"(p0));
            asm volatile("cp.async.cg.shared.global [%0], [%1], 16;\n" :: "r"(d + 512), "l"(p1));
        }
        asm volatile("cp.async.commit_group;\n" ::);
    }

    // --- compute: overlap group 1 flight with group 0 compute ---
#pragma unroll
    for (int g = 0; g < 2; ++g) {
        if (g == 0) asm volatile("cp.async.wait_group 1;\n" ::);
        else        asm volatile("cp.async.wait_group 0;\n" ::);
        __syncwarp();
#pragma unroll
        for (int j = 0; j < 2; ++j) {
            const int k = w * 4 + g * 2 + j;
            const int4 s = sp4[k];
            const float w0 = __int_as_float(s.y);
            const float w1 = __int_as_float(s.w);
            const float2* p = (const float2*)&stage[k][0];   // 4 rows x 32 f2
            float2 a00 = p[l];          // batches 2l,2l+1 of row i0
            float2 a01 = p[32 + l];     // row i0+1
            float2 a10 = p[64 + l];     // row i1
            float2 a11 = p[96 + l];     // row i1+1

            float2 r;
            r.x = (1.0f - fmaf(a01.x - a00.x, w0, a00.x)) * (1.0f - fmaf(a11.x - a10.x, w1, a10.x));
            r.y = (1.0f - fmaf(a01.y - a00.y, w0, a00.y)) * (1.0f - fmaf(a11.y - a10.y, w1, a10.y));
            *(float2*)&tile[k][2 * l] = r;
        }
    }
    __syncthreads();

    // --- epilogue: coalesced streaming writes, float2 over n ---
    const int c2 = tid & 15;             // n-pair: cols 2c2, 2c2+1 (32 n -> 16 pairs)
    const int rb = tid >> 4;             // 0..15
    for (int r = rb; r < HALF_B; r += 16) {
        float2 v;
        v.x = tile[2 * c2 + 0][r];
        v.y = tile[2 * c2 + 1][r];
        float2* dst = (float2*)&out[(size_t)(rowBase + r) * N_OUTP + n0 + 2 * c2];
        __stcs(dst, v);
    }
}

// ---------------------------------------------------------------------------
// Launch 1: prep of batches 0..63 + full sampler.
// Grid (512, 2), 256 threads.
// ---------------------------------------------------------------------------
__global__ void __launch_bounds__(256) prep_lo_kernel(const float* __restrict__ act,
                                                      const float* __restrict__ sp_in) {
    __shared__ __align__(128) char raw[16384];
    const int tid = threadIdx.x;

    // --- sampler: 128 samples per block, 1024 blocks -> 131072 ---
    if (tid < 128) {
        int m = (blockIdx.y * 512 + blockIdx.x) * 128 + tid;
        float sp = sp_in[m];
        sp = fminf(fmaxf(sp, 0.0f), 1.0f);
        int i = (int)(sp * 65535.0f);
        i = max(0, min(i, N_IN - 2));
        // Exact searchsorted-left fix-up: largest i with x[i] < sp (clamped)
        while (i > 0 && gridx(i) >= sp) --i;
        while (i < N_IN - 2 && gridx(i + 1) < sp) ++i;
        float xi = gridx(i);
        float dx = gridx(i + 1) - xi;
        float w  = (sp - xi) / (dx + 1e-8f);
        g_pairs[m] = make_int2(i, __float_as_int(w));
    }

    prep_half(act, g_lo, 0, blockIdx.x, blockIdx.y, tid, raw);
}

// ---------------------------------------------------------------------------
// Launch 2 (combo): blocks 0..1023 = prep of batches 64..127 (DRAM-bound),
// blocks 1024..3071 = main over batches 0..63 (L2-bound). Independent roles
// run concurrently; prep-role blocks come first so they start in wave 1.
// ---------------------------------------------------------------------------
__global__ void __launch_bounds__(256) combo_kernel(const float* __restrict__ act,
                                                    float* __restrict__ out) {
    __shared__ __align__(128) char raw[SM_MAIN];
    const int bx  = blockIdx.x;
    const int tid = threadIdx.x;
    if (bx < 1024) {
        prep_half(act, g_hi, HALF_B, bx & 511, bx >> 9, tid, raw);
    } else {
        main_half(out, (const char*)g_lo, 0, bx - 1024, tid, raw);
    }
}

// ---------------------------------------------------------------------------
// Launch 3: main over batches 64..127.
// ---------------------------------------------------------------------------
__global__ void __launch_bounds__(256) main_hi_kernel(float* __restrict__ out) {
    __shared__ __align__(128) char raw[SM_MAIN];
    main_half(out, (const char*)g_hi, HALF_B, blockIdx.x, threadIdx.x, raw);
}

// ---------------------------------------------------------------------------
extern "C" void kernel_launch(void* const* d_in, const int* in_sizes, int n_in,
                              void* d_out, int out_size) {
    const float* act = (const float*)d_in[0];   // (128, 65536) f32
    const float* sp  = (const float*)d_in[1];   // (65536, 2, 1) f32
    float* out       = (float*)d_out;           // (128, 65536) f32

    prep_lo_kernel<<<dim3(512, 2), 256>>>(act, sp);
    combo_kernel<<<1024 + N_OUTP / TN, 256>>>(act, out);
    main_hi_kernel<<<N_OUTP / TN, 256>>>(out);
}